// round 1
// baseline (speedup 1.0000x reference)
#include <cuda_runtime.h>
#include <math.h>

#define NB 64
#define NS 512
#define NF 1024

static __device__ float g_P[NB * NS * NF];  // x_proj, layout [b][s][h]
static __device__ float g_H[NB * NS * NF];  // hidden states, layout [b][s][h]

typedef unsigned long long ull;

__device__ __forceinline__ ull pack2(float x) {
    ull r;
    asm("mov.b64 %0, {%1, %1};" : "=l"(r) : "f"(x));
    return r;
}
__device__ __forceinline__ float2 unpack2(ull v) {
    float2 r;
    asm("mov.b64 {%0, %1}, %2;" : "=f"(r.x), "=f"(r.y) : "l"(v));
    return r;
}
__device__ __forceinline__ void fma2(ull& d, ull a, ull b) {
    asm("fma.rn.f32x2 %0, %1, %2, %0;" : "+l"(d) : "l"(a), "l"(b));
}

// ---------------------------------------------------------------------------
// Big GEMM with bias: C[M x 1024] = A[M x 1024] @ W[:, :1024]^T + bias
//   A row-major lda=1024, W row-major with leading dim ldw (2048 for W_ih,
//   1024 for W_ho), C row-major ldc=1024.
// CTA tile 64(M) x 128(N), BK=16, 256 threads, 4x8 outputs/thread via f32x2.
// ---------------------------------------------------------------------------
__global__ void __launch_bounds__(256, 1) gemm_bias(
    const float* __restrict__ A, const float* __restrict__ W, int ldw,
    const float* __restrict__ bias, float* __restrict__ C)
{
    __shared__ __align__(16) float As[16][68];
    __shared__ __align__(16) float Bs[16][136];

    const int bm = blockIdx.y * 64;
    const int bn = blockIdx.x * 128;
    const int tid = threadIdx.x;

    // loader mapping
    const int arow = tid >> 2, acol = (tid & 3) << 2;   // 64 rows x 16k, 4 floats/thread
    const int brow = tid >> 1, bcol = (tid & 1) << 3;   // 128 rows x 16k, 8 floats/thread
    const float* Ap = A + (size_t)(bm + arow) * 1024 + acol;
    const float* Wp = W + (size_t)(bn + brow) * ldw + bcol;

    // compute mapping: 16x16 thread grid, thread tile 4m x 8n
    const int tx = tid & 15, ty = tid >> 4;
    const int n0 = tx * 8, m0 = ty * 4;

    ull acc[4][4];
#pragma unroll
    for (int i = 0; i < 4; i++)
#pragma unroll
        for (int j = 0; j < 4; j++) acc[i][j] = 0ull;

    for (int k0 = 0; k0 < 1024; k0 += 16) {
        float4 av  = *(const float4*)(Ap + k0);
        float4 bv0 = *(const float4*)(Wp + k0);
        float4 bv1 = *(const float4*)(Wp + k0 + 4);
        __syncthreads();
        As[acol + 0][arow] = av.x;
        As[acol + 1][arow] = av.y;
        As[acol + 2][arow] = av.z;
        As[acol + 3][arow] = av.w;
        Bs[bcol + 0][brow] = bv0.x;
        Bs[bcol + 1][brow] = bv0.y;
        Bs[bcol + 2][brow] = bv0.z;
        Bs[bcol + 3][brow] = bv0.w;
        Bs[bcol + 4][brow] = bv1.x;
        Bs[bcol + 5][brow] = bv1.y;
        Bs[bcol + 6][brow] = bv1.z;
        Bs[bcol + 7][brow] = bv1.w;
        __syncthreads();
#pragma unroll
        for (int k = 0; k < 16; k++) {
            float4 a4 = *(const float4*)&As[k][m0];
            ull a0 = pack2(a4.x), a1 = pack2(a4.y), a2 = pack2(a4.z), a3 = pack2(a4.w);
            ulonglong2 bq0 = *(const ulonglong2*)&Bs[k][n0];
            ulonglong2 bq1 = *(const ulonglong2*)&Bs[k][n0 + 4];
            fma2(acc[0][0], a0, bq0.x); fma2(acc[0][1], a0, bq0.y);
            fma2(acc[0][2], a0, bq1.x); fma2(acc[0][3], a0, bq1.y);
            fma2(acc[1][0], a1, bq0.x); fma2(acc[1][1], a1, bq0.y);
            fma2(acc[1][2], a1, bq1.x); fma2(acc[1][3], a1, bq1.y);
            fma2(acc[2][0], a2, bq0.x); fma2(acc[2][1], a2, bq0.y);
            fma2(acc[2][2], a2, bq1.x); fma2(acc[2][3], a2, bq1.y);
            fma2(acc[3][0], a3, bq0.x); fma2(acc[3][1], a3, bq0.y);
            fma2(acc[3][2], a3, bq1.x); fma2(acc[3][3], a3, bq1.y);
        }
    }

    float bb[8];
#pragma unroll
    for (int j = 0; j < 8; j++) bb[j] = bias[bn + n0 + j];

#pragma unroll
    for (int i = 0; i < 4; i++) {
        float2 p0 = unpack2(acc[i][0]);
        float2 p1 = unpack2(acc[i][1]);
        float2 p2 = unpack2(acc[i][2]);
        float2 p3 = unpack2(acc[i][3]);
        float4 v0 = make_float4(p0.x + bb[0], p0.y + bb[1], p1.x + bb[2], p1.y + bb[3]);
        float4 v1 = make_float4(p2.x + bb[4], p2.y + bb[5], p3.x + bb[6], p3.y + bb[7]);
        float* cp = C + (size_t)(bm + m0 + i) * 1024 + bn + n0;
        *(float4*)cp = v0;
        *(float4*)(cp + 4) = v1;
    }
}

// ---------------------------------------------------------------------------
// One recurrence step:
//   h_new[b][n] = tanh( g_P[b][s][n] + sum_j h_prev[b][j] * W_h[n][j] )
//   written to g_H[b][s][n].
// h_prev row for batch b: hbase + b*hbstride + hoff
// CTA tile 32(M=batch) x 16(N), grid (64, 2) = 128 CTAs, 128 threads.
// Thread tile: one m-pair (packed along M) x 2 n columns, f32x2 FMA.
// Ws2 holds W_h values pre-duplicated as (w,w) pairs.
// ---------------------------------------------------------------------------
__global__ void __launch_bounds__(128, 1) rnn_step(
    const float* __restrict__ Wih,
    const float* __restrict__ hbase, int hbstride, int hoff,
    int s)
{
    __shared__ __align__(16) float Hs[64][34];
    __shared__ __align__(16) ull Ws2[64][16];

    const int bn = blockIdx.x * 16;
    const int bm = blockIdx.y * 32;
    const int tid = threadIdx.x;

    // loader mapping
    const int hrow = tid >> 2, hcol = (tid & 3) << 4;   // 32 rows x 64k, 16 floats/thread
    const int wrow = tid >> 3, wcol = (tid & 7) << 3;   // 16 rows x 64k, 8 floats/thread
    const float* hp = hbase + (size_t)(bm + hrow) * hbstride + hoff + hcol;
    const float* wp = Wih + (size_t)(bn + wrow) * 2048 + 1024 + wcol;  // W_h part

    // compute mapping
    const int tx = tid & 7, mp = tid >> 3;
    const int n0 = tx * 2, m0 = mp * 2;

    ull acc0 = 0ull, acc1 = 0ull;

    for (int k0 = 0; k0 < 1024; k0 += 64) {
        float4 h0 = *(const float4*)(hp + k0);
        float4 h1 = *(const float4*)(hp + k0 + 4);
        float4 h2 = *(const float4*)(hp + k0 + 8);
        float4 h3 = *(const float4*)(hp + k0 + 12);
        float4 w0 = *(const float4*)(wp + k0);
        float4 w1 = *(const float4*)(wp + k0 + 4);
        __syncthreads();
        Hs[hcol + 0][hrow] = h0.x;  Hs[hcol + 1][hrow] = h0.y;
        Hs[hcol + 2][hrow] = h0.z;  Hs[hcol + 3][hrow] = h0.w;
        Hs[hcol + 4][hrow] = h1.x;  Hs[hcol + 5][hrow] = h1.y;
        Hs[hcol + 6][hrow] = h1.z;  Hs[hcol + 7][hrow] = h1.w;
        Hs[hcol + 8][hrow] = h2.x;  Hs[hcol + 9][hrow] = h2.y;
        Hs[hcol + 10][hrow] = h2.z; Hs[hcol + 11][hrow] = h2.w;
        Hs[hcol + 12][hrow] = h3.x; Hs[hcol + 13][hrow] = h3.y;
        Hs[hcol + 14][hrow] = h3.z; Hs[hcol + 15][hrow] = h3.w;
        Ws2[wcol + 0][wrow] = pack2(w0.x);
        Ws2[wcol + 1][wrow] = pack2(w0.y);
        Ws2[wcol + 2][wrow] = pack2(w0.z);
        Ws2[wcol + 3][wrow] = pack2(w0.w);
        Ws2[wcol + 4][wrow] = pack2(w1.x);
        Ws2[wcol + 5][wrow] = pack2(w1.y);
        Ws2[wcol + 6][wrow] = pack2(w1.z);
        Ws2[wcol + 7][wrow] = pack2(w1.w);
        __syncthreads();
#pragma unroll
        for (int k = 0; k < 64; k++) {
            ull a = *(const ull*)&Hs[k][m0];                       // (h[m0], h[m0+1])
            ulonglong2 b = *(const ulonglong2*)&Ws2[k][n0];        // dup'd w[n0], w[n0+1]
            fma2(acc0, a, b.x);
            fma2(acc1, a, b.y);
        }
    }

    // epilogue: acc0 = (C[m0][n0], C[m0+1][n0]); acc1 = (C[m0][n0+1], C[m0+1][n0+1])
    float2 c0 = unpack2(acc0);
    float2 c1 = unpack2(acc1);
    size_t r0 = ((size_t)(bm + m0) * NS + s) * NF + bn + n0;
    size_t r1 = ((size_t)(bm + m0 + 1) * NS + s) * NF + bn + n0;
    float2 p0 = *(const float2*)&g_P[r0];
    float2 p1 = *(const float2*)&g_P[r1];
    float2 o0 = make_float2(tanhf(p0.x + c0.x), tanhf(p0.y + c1.x));
    float2 o1 = make_float2(tanhf(p1.x + c0.y), tanhf(p1.y + c1.y));
    *(float2*)&g_H[r0] = o0;
    *(float2*)&g_H[r1] = o1;
}

extern "C" void kernel_launch(void* const* d_in, const int* in_sizes, int n_in,
                              void* d_out, int out_size)
{
    const float* x   = (const float*)d_in[0];
    const float* h0  = (const float*)d_in[1];
    const float* Wih = (const float*)d_in[2];
    const float* bih = (const float*)d_in[3];
    const float* Who = (const float*)d_in[4];
    const float* bho = (const float*)d_in[5];
    float* out = (float*)d_out;

    float *pP = nullptr, *pH = nullptr;
    cudaGetSymbolAddress((void**)&pP, g_P);
    cudaGetSymbolAddress((void**)&pH, g_H);

    // 1) x_proj: g_P[b][s][h] = x[b][s][:] . W_ih[h][:1024] + b_ih[h]
    //    rows r = b*512 + s match x's natural layout.
    gemm_bias<<<dim3(8, 512), 256>>>(x, Wih, 2048, bih, pP);

    // 2) sequential recurrence, one launch per step
    for (int s = 0; s < NS; s++) {
        const float* hb = (s == 0) ? h0 : pH;
        int bstr = (s == 0) ? NF : NS * NF;
        int hoff = (s == 0) ? 0 : (s - 1) * NF;
        rnn_step<<<dim3(64, 2), 128>>>(Wih, hb, bstr, hoff, s);
    }

    // 3) output projection: out[b][s][o] = g_H[b][s][:] . W_ho[o][:] + b_ho[o]
    gemm_bias<<<dim3(8, 512), 256>>>(pH, Who, 1024, bho, out);
}

// round 2
// speedup vs baseline: 1.4212x; 1.4212x over previous
#include <cuda_runtime.h>
#include <math.h>

#define NB 64
#define NS 512
#define NF 1024

static __device__ float g_P[NB * NS * NF];      // x_proj, layout [b][s][h]
static __device__ float g_H[NB * NS * NF];      // hidden states, layout [b][s][h]
static __device__ float g_ring[2 * 1032 * 64];  // transposed h ring: [slot][k][b], padded rows
static __device__ unsigned g_ctr[NS];           // per-step arrival counters

typedef unsigned long long ull;

__device__ __forceinline__ ull pack2(float x) {
    ull r;
    asm("mov.b64 %0, {%1, %1};" : "=l"(r) : "f"(x));
    return r;
}
__device__ __forceinline__ float2 unpack2(ull v) {
    float2 r;
    asm("mov.b64 {%0, %1}, %2;" : "=f"(r.x), "=f"(r.y) : "l"(v));
    return r;
}
__device__ __forceinline__ void fma2(ull& d, ull a, ull b) {
    asm("fma.rn.f32x2 %0, %1, %2, %0;" : "+l"(d) : "l"(a), "l"(b));
}
__device__ __forceinline__ void fma2f(ull& d, float ax, float ay, ull b) {
    asm("{\n\t.reg .b64 t;\n\tmov.b64 t, {%1,%2};\n\tfma.rn.f32x2 %0, t, %3, %0;\n\t}"
        : "+l"(d) : "f"(ax), "f"(ay), "l"(b));
}

// ---------------------------------------------------------------------------
// Big GEMM with bias: C[M x 1024] = A[M x 1024] @ W[:, :1024]^T + bias
// (unchanged from round 1 — known correct; profile this round)
// ---------------------------------------------------------------------------
__global__ void __launch_bounds__(256, 1) gemm_bias(
    const float* __restrict__ A, const float* __restrict__ W, int ldw,
    const float* __restrict__ bias, float* __restrict__ C)
{
    __shared__ __align__(16) float As[16][68];
    __shared__ __align__(16) float Bs[16][136];

    const int bm = blockIdx.y * 64;
    const int bn = blockIdx.x * 128;
    const int tid = threadIdx.x;

    const int arow = tid >> 2, acol = (tid & 3) << 2;
    const int brow = tid >> 1, bcol = (tid & 1) << 3;
    const float* Ap = A + (size_t)(bm + arow) * 1024 + acol;
    const float* Wp = W + (size_t)(bn + brow) * ldw + bcol;

    const int tx = tid & 15, ty = tid >> 4;
    const int n0 = tx * 8, m0 = ty * 4;

    ull acc[4][4];
#pragma unroll
    for (int i = 0; i < 4; i++)
#pragma unroll
        for (int j = 0; j < 4; j++) acc[i][j] = 0ull;

    for (int k0 = 0; k0 < 1024; k0 += 16) {
        float4 av  = *(const float4*)(Ap + k0);
        float4 bv0 = *(const float4*)(Wp + k0);
        float4 bv1 = *(const float4*)(Wp + k0 + 4);
        __syncthreads();
        As[acol + 0][arow] = av.x;
        As[acol + 1][arow] = av.y;
        As[acol + 2][arow] = av.z;
        As[acol + 3][arow] = av.w;
        Bs[bcol + 0][brow] = bv0.x;
        Bs[bcol + 1][brow] = bv0.y;
        Bs[bcol + 2][brow] = bv0.z;
        Bs[bcol + 3][brow] = bv0.w;
        Bs[bcol + 4][brow] = bv1.x;
        Bs[bcol + 5][brow] = bv1.y;
        Bs[bcol + 6][brow] = bv1.z;
        Bs[bcol + 7][brow] = bv1.w;
        __syncthreads();
#pragma unroll
        for (int k = 0; k < 16; k++) {
            float4 a4 = *(const float4*)&As[k][m0];
            ull a0 = pack2(a4.x), a1 = pack2(a4.y), a2 = pack2(a4.z), a3 = pack2(a4.w);
            ulonglong2 bq0 = *(const ulonglong2*)&Bs[k][n0];
            ulonglong2 bq1 = *(const ulonglong2*)&Bs[k][n0 + 4];
            fma2(acc[0][0], a0, bq0.x); fma2(acc[0][1], a0, bq0.y);
            fma2(acc[0][2], a0, bq1.x); fma2(acc[0][3], a0, bq1.y);
            fma2(acc[1][0], a1, bq0.x); fma2(acc[1][1], a1, bq0.y);
            fma2(acc[1][2], a1, bq1.x); fma2(acc[1][3], a1, bq1.y);
            fma2(acc[2][0], a2, bq0.x); fma2(acc[2][1], a2, bq0.y);
            fma2(acc[2][2], a2, bq1.x); fma2(acc[2][3], a2, bq1.y);
            fma2(acc[3][0], a3, bq0.x); fma2(acc[3][1], a3, bq0.y);
            fma2(acc[3][2], a3, bq1.x); fma2(acc[3][3], a3, bq1.y);
        }
    }

    float bb[8];
#pragma unroll
    for (int j = 0; j < 8; j++) bb[j] = bias[bn + n0 + j];

#pragma unroll
    for (int i = 0; i < 4; i++) {
        float2 p0 = unpack2(acc[i][0]);
        float2 p1 = unpack2(acc[i][1]);
        float2 p2 = unpack2(acc[i][2]);
        float2 p3 = unpack2(acc[i][3]);
        float4 v0 = make_float4(p0.x + bb[0], p0.y + bb[1], p1.x + bb[2], p1.y + bb[3]);
        float4 v1 = make_float4(p2.x + bb[4], p2.y + bb[5], p3.x + bb[6], p3.y + bb[7]);
        float* cp = C + (size_t)(bm + m0 + i) * 1024 + bn + n0;
        *(float4*)cp = v0;
        *(float4*)(cp + 4) = v1;
    }
}

// ---------------------------------------------------------------------------
// Init: zero the per-step counters; transpose h0 (=[b][k]) into ring slot 1
// (so step 0 reads slot (0+1)&1 = 1).
// ---------------------------------------------------------------------------
__global__ void scan_init(const float* __restrict__ h0)
{
    int idx = blockIdx.x * 256 + threadIdx.x;   // 0 .. 65535
    int k = idx >> 6, b = idx & 63;
    g_ring[1032 * 64 + k * 64 + b] = h0[b * 1024 + k];
    if (idx < NS) g_ctr[idx] = 0u;
}

// ---------------------------------------------------------------------------
// Persistent recurrence scan.
//   128 CTAs x 256 threads. CTA c owns n-slice [c*8, c*8+8) of W_h, kept in
//   SMEM as (w,w)-duplicated f32x2 pairs (64 KB). Warp w reduces k-range
//   [w*128, w*128+128); thread tile = 4 batch-pairs x 2 n. Cross-warp
//   reduction via 16 KB SMEM. h flows through a 2-slot transposed ring in
//   global memory ([k][b], L2-resident). Grid-wide sync per step via
//   per-step counters.
// ---------------------------------------------------------------------------
__global__ void __launch_bounds__(256, 1) rnn_scan(const float* __restrict__ Wih)
{
    extern __shared__ ull sm[];
    ull* wsm = sm;           // [1024][8] duplicated W_h slice
    ull* red = sm + 8192;    // [8 warps][256] partials

    const int tid = threadIdx.x;
    const int warp = tid >> 5, lane = tid & 31;
    const int bpg = lane & 7;            // batch-pair group (8 batches)
    const int ng  = lane >> 3;           // n-pair group
    const int n0  = 2 * ng;
    const int b0l = bpg * 8;             // first batch for loads
    const int kbase = warp * 128;
    const int NB0 = blockIdx.x * 8;

    // Load + duplicate this CTA's W_h slice into SMEM (once per launch).
    for (int idx = tid; idx < 8192; idx += 256) {
        int k = idx >> 3, n = idx & 7;
        wsm[idx] = pack2(Wih[(size_t)(NB0 + n) * 2048 + 1024 + k]);
    }
    __syncthreads();

    // Epilogue (reader-role) decode for this thread.
    const int rl = tid >> 3, rq = tid & 7;
    const int rj = rq >> 2, ri = rq & 3;
    const int rn = NB0 + 2 * (rl >> 3) + rj;           // global n
    const int rb = 2 * (4 * (rl & 7) + ri);            // even batch
    const size_t pbase0 = ((size_t)rb * NS) * NF + rn;
    const size_t pbase1 = ((size_t)(rb + 1) * NS) * NF + rn;

    for (int s = 0; s < NS; ++s) {
        const float* __restrict__ hq = g_ring + ((s + 1) & 1) * (1032 * 64) + b0l;

        // Prefetch this thread's x_proj values for the epilogue.
        float pr0 = __ldg(&g_P[pbase0 + (size_t)s * NF]);
        float pr1 = __ldg(&g_P[pbase1 + (size_t)s * NF]);

        ull acc[2][4];
#pragma unroll
        for (int j = 0; j < 2; j++)
#pragma unroll
            for (int i = 0; i < 4; i++) acc[j][i] = 0ull;

        // Software-pipelined k loop, prefetch depth 4 (ring rows are padded,
        // so over-reads past k=1023 are harmless).
        float4 f0[4], f1[4];
#pragma unroll
        for (int j = 0; j < 4; ++j) {
            f0[j] = *(const float4*)(hq + (kbase + j) * 64);
            f1[j] = *(const float4*)(hq + (kbase + j) * 64 + 4);
        }
#pragma unroll 4
        for (int kk = 0; kk < 128; ++kk) {
            const int slot = kk & 3;
            float4 h0 = f0[slot], h1 = f1[slot];
            f0[slot] = *(const float4*)(hq + (kbase + kk + 4) * 64);
            f1[slot] = *(const float4*)(hq + (kbase + kk + 4) * 64 + 4);
            ulonglong2 wv = *(const ulonglong2*)(wsm + (kbase + kk) * 8 + n0);
            fma2f(acc[0][0], h0.x, h0.y, wv.x);
            fma2f(acc[0][1], h0.z, h0.w, wv.x);
            fma2f(acc[0][2], h1.x, h1.y, wv.x);
            fma2f(acc[0][3], h1.z, h1.w, wv.x);
            fma2f(acc[1][0], h0.x, h0.y, wv.y);
            fma2f(acc[1][1], h0.z, h0.w, wv.y);
            fma2f(acc[1][2], h1.x, h1.y, wv.y);
            fma2f(acc[1][3], h1.z, h1.w, wv.y);
        }

        // Stash partials, reduce across the 8 warps.
        ull* rp = red + warp * 256 + lane * 8;
#pragma unroll
        for (int q = 0; q < 8; ++q) rp[q] = acc[q >> 2][q & 3];
        __syncthreads();

        float sx = 0.f, sy = 0.f;
#pragma unroll
        for (int w2 = 0; w2 < 8; ++w2) {
            float2 v = unpack2(red[w2 * 256 + tid]);
            sx += v.x; sy += v.y;
        }
        float r0 = tanhf(sx + pr0);
        float r1 = tanhf(sy + pr1);

        // Write h both row-major (for output GEMM) and transposed (ring).
        g_H[pbase0 + (size_t)s * NF] = r0;
        g_H[pbase1 + (size_t)s * NF] = r1;
        float* rc = g_ring + (s & 1) * (1032 * 64);
        *(float2*)(rc + rn * 64 + rb) = make_float2(r0, r1);

        // Grid-wide barrier (skip after the final step).
        if (s != NS - 1) {
            __syncthreads();
            if (tid == 0) {
                __threadfence();
                atomicAdd(&g_ctr[s], 1u);
                unsigned v;
                do {
                    asm volatile("ld.acquire.gpu.global.u32 %0, [%1];"
                                 : "=r"(v) : "l"(&g_ctr[s]));
                } while (v < 128u);
            }
            __syncthreads();
        }
    }
}

extern "C" void kernel_launch(void* const* d_in, const int* in_sizes, int n_in,
                              void* d_out, int out_size)
{
    const float* x   = (const float*)d_in[0];
    const float* h0  = (const float*)d_in[1];
    const float* Wih = (const float*)d_in[2];
    const float* bih = (const float*)d_in[3];
    const float* Who = (const float*)d_in[4];
    const float* bho = (const float*)d_in[5];
    float* out = (float*)d_out;

    float *pP = nullptr, *pH = nullptr;
    cudaGetSymbolAddress((void**)&pP, g_P);
    cudaGetSymbolAddress((void**)&pH, g_H);

    static bool attr_done = false;
    if (!attr_done) {
        cudaFuncSetAttribute(rnn_scan, cudaFuncAttributeMaxDynamicSharedMemorySize, 81920);
        attr_done = true;
    }

    // 0) init ring slot 1 with transposed h0; zero barrier counters
    scan_init<<<256, 256>>>(h0);

    // 1) x_proj: g_P[b][s][h] = x[b][s][:] . W_x[h][:] + b_ih[h]
    gemm_bias<<<dim3(8, 512), 256>>>(x, Wih, 2048, bih, pP);

    // 2) persistent recurrence scan (single launch, grid-synced steps)
    rnn_scan<<<128, 256, 81920>>>(Wih);

    // 3) output projection
    gemm_bias<<<dim3(8, 512), 256>>>(pH, Who, 1024, bho, out);
}

// round 3
// speedup vs baseline: 1.9371x; 1.3630x over previous
#include <cuda_runtime.h>
#include <math.h>

#define NB 64
#define NS 512
#define NF 1024

static __device__ float g_P[NB * NS * NF];      // x_proj, [b][s][h]
static __device__ float g_H[NB * NS * NF];      // hidden states, [b][s][h]
static __device__ float g_ring[2 * 1032 * 64];  // transposed h ring: [slot][k][b]
static __device__ unsigned g_ctr[NS];           // per-step arrival counters

typedef unsigned long long ull;

__device__ __forceinline__ ull pack2(float x) {
    ull r;
    asm("mov.b64 %0, {%1, %1};" : "=l"(r) : "f"(x));
    return r;
}
__device__ __forceinline__ float2 unpack2(ull v) {
    float2 r;
    asm("mov.b64 {%0, %1}, %2;" : "=f"(r.x), "=f"(r.y) : "l"(v));
    return r;
}
__device__ __forceinline__ void fma2(ull& d, ull a, ull b) {
    asm("fma.rn.f32x2 %0, %1, %2, %0;" : "+l"(d) : "l"(a), "l"(b));
}

// ---------------------------------------------------------------------------
// Big GEMM with bias: C[M x 1024] = A[M x 1024] @ W[:, :1024]^T + bias
// CTA tile 128m x 128n, BK=16, 256 threads, thread tile 8m x 8n.
// A duplicated in registers (f32x2 (a,a)), B consumed as adjacent n-pairs.
// 2 CTAs/SM for latency hiding.
// ---------------------------------------------------------------------------
__global__ void __launch_bounds__(256, 2) gemm_bias(
    const float* __restrict__ A, const float* __restrict__ W, int ldw,
    const float* __restrict__ bias, float* __restrict__ C)
{
    __shared__ __align__(16) float As[16][132];
    __shared__ __align__(16) float Bs[16][132];

    const int bm = blockIdx.y * 128;
    const int bn = blockIdx.x * 128;
    const int tid = threadIdx.x;

    // loader mapping: 128 rows x 16 k, 8 floats/thread
    const int lrow = tid >> 1, lkc = (tid & 1) << 3;
    const float* Ap = A + (size_t)(bm + lrow) * 1024 + lkc;
    const float* Wp = W + (size_t)(bn + lrow) * ldw + lkc;

    // compute mapping: 16x16 thread grid, thread tile 8m x 8n (n in 2 groups)
    const int tx = tid & 15, ty = tid >> 4;
    const int m0 = ty * 8;
    const int nA = tx * 4;        // group 0: n in [nA, nA+4)
    const int nBq = 64 + tx * 4;  // group 1

    ull acc[8][4];
#pragma unroll
    for (int i = 0; i < 8; i++)
#pragma unroll
        for (int j = 0; j < 4; j++) acc[i][j] = 0ull;

    for (int k0 = 0; k0 < 1024; k0 += 16) {
        float4 av0 = *(const float4*)(Ap + k0);
        float4 av1 = *(const float4*)(Ap + k0 + 4);
        float4 bv0 = *(const float4*)(Wp + k0);
        float4 bv1 = *(const float4*)(Wp + k0 + 4);
        __syncthreads();
        As[lkc + 0][lrow] = av0.x; As[lkc + 1][lrow] = av0.y;
        As[lkc + 2][lrow] = av0.z; As[lkc + 3][lrow] = av0.w;
        As[lkc + 4][lrow] = av1.x; As[lkc + 5][lrow] = av1.y;
        As[lkc + 6][lrow] = av1.z; As[lkc + 7][lrow] = av1.w;
        Bs[lkc + 0][lrow] = bv0.x; Bs[lkc + 1][lrow] = bv0.y;
        Bs[lkc + 2][lrow] = bv0.z; Bs[lkc + 3][lrow] = bv0.w;
        Bs[lkc + 4][lrow] = bv1.x; Bs[lkc + 5][lrow] = bv1.y;
        Bs[lkc + 6][lrow] = bv1.z; Bs[lkc + 7][lrow] = bv1.w;
        __syncthreads();
#pragma unroll
        for (int k = 0; k < 16; k++) {
            float4 a0 = *(const float4*)&As[k][m0];
            float4 a1 = *(const float4*)&As[k][m0 + 4];
            ull ad[8];
            ad[0] = pack2(a0.x); ad[1] = pack2(a0.y);
            ad[2] = pack2(a0.z); ad[3] = pack2(a0.w);
            ad[4] = pack2(a1.x); ad[5] = pack2(a1.y);
            ad[6] = pack2(a1.z); ad[7] = pack2(a1.w);
            ulonglong2 bp0 = *(const ulonglong2*)&Bs[k][nA];   // pairs (nA,nA+1),(nA+2,nA+3)
            ulonglong2 bp1 = *(const ulonglong2*)&Bs[k][nBq];
#pragma unroll
            for (int m = 0; m < 8; m++) {
                fma2(acc[m][0], ad[m], bp0.x);
                fma2(acc[m][1], ad[m], bp0.y);
                fma2(acc[m][2], ad[m], bp1.x);
                fma2(acc[m][3], ad[m], bp1.y);
            }
        }
    }

    float4 bbA = *(const float4*)(bias + bn + nA);
    float4 bbB = *(const float4*)(bias + bn + nBq);

#pragma unroll
    for (int m = 0; m < 8; m++) {
        float2 c0 = unpack2(acc[m][0]);
        float2 c1 = unpack2(acc[m][1]);
        float2 c2 = unpack2(acc[m][2]);
        float2 c3 = unpack2(acc[m][3]);
        float* cp = C + (size_t)(bm + m0 + m) * 1024 + bn;
        *(float4*)(cp + nA)  = make_float4(c0.x + bbA.x, c0.y + bbA.y,
                                           c1.x + bbA.z, c1.y + bbA.w);
        *(float4*)(cp + nBq) = make_float4(c2.x + bbB.x, c2.y + bbB.y,
                                           c3.x + bbB.z, c3.y + bbB.w);
    }
}

// ---------------------------------------------------------------------------
// Init: zero per-step counters; transpose h0 into ring slot 1.
// ---------------------------------------------------------------------------
__global__ void scan_init(const float* __restrict__ h0)
{
    int idx = blockIdx.x * 256 + threadIdx.x;   // 0 .. 65535
    int k = idx >> 6, b = idx & 63;
    g_ring[1032 * 64 + k * 64 + b] = h0[b * 1024 + k];
    if (idx < NS) g_ctr[idx] = 0u;
}

// ---------------------------------------------------------------------------
// Persistent recurrence scan: 128 CTAs x 512 threads (16 warps).
// CTA owns n-slice [c*8, c*8+8); W_h slice dup'd in SMEM (64 KB).
// Warp w reduces k in [w*64, w*64+64). Thread: 8 batches (4 f32x2 pairs,
// loaded directly as ulonglong2 from the transposed ring) x 2 n.
// Depth-8 software pipeline covers L2 latency. Cross-warp reduce via 32 KB
// SMEM in a lane-contiguous (conflict-free) layout.
// ---------------------------------------------------------------------------
__global__ void __launch_bounds__(512, 1) rnn_scan(const float* __restrict__ Wih)
{
    extern __shared__ ull sm[];
    ull* wsm = sm;           // [1024 k][8 n] duplicated W_h slice (64 KB)
    ull* red = sm + 8192;    // [16 w][8 q][32 lane] partials (32 KB)

    const int tid  = threadIdx.x;
    const int warp = tid >> 5, lane = tid & 31;
    const int bpg = lane & 7;            // batch group: batches [8*bpg, 8*bpg+8)
    const int ng  = lane >> 3;           // n-pair group (0..3)
    const int kbase = warp * 64;
    const int NB0 = blockIdx.x * 8;

    // Load + duplicate this CTA's W_h slice (once per launch).
    for (int idx = tid; idx < 8192; idx += 512) {
        int k = idx >> 3, n = idx & 7;
        wsm[idx] = pack2(Wih[(size_t)(NB0 + n) * 2048 + 1024 + k]);
    }

    // Epilogue decode (threads 0..255 each own one f32x2 output pair).
    const int rq = tid >> 5, rl = tid & 31;      // valid when tid < 256
    const int rn = NB0 + 2 * (rl >> 3) + (rq >> 2);
    const int rb = 2 * (4 * (rl & 7) + (rq & 3));
    const size_t pb0 = ((size_t)rb * NS) * NF + rn;
    const size_t pb1 = ((size_t)(rb + 1) * NS) * NF + rn;

    __syncthreads();

    for (int s = 0; s < NS; ++s) {
        const float* __restrict__ hq =
            g_ring + ((s + 1) & 1) * (1032 * 64) + 8 * bpg;

        float pr0 = 0.f, pr1 = 0.f;
        if (tid < 256) {
            pr0 = __ldg(&g_P[pb0 + (size_t)s * NF]);
            pr1 = __ldg(&g_P[pb1 + (size_t)s * NF]);
        }

        ull acc[2][4];
#pragma unroll
        for (int j = 0; j < 2; j++)
#pragma unroll
            for (int i = 0; i < 4; i++) acc[j][i] = 0ull;

        // depth-8 pipelined k loop (ring rows padded: over-read is harmless)
        ulonglong2 p0[8], p1[8];
#pragma unroll
        for (int j = 0; j < 8; ++j) {
            p0[j] = *(const ulonglong2*)(hq + (kbase + j) * 64);
            p1[j] = *(const ulonglong2*)(hq + (kbase + j) * 64 + 4);
        }
#pragma unroll 8
        for (int kk = 0; kk < 64; ++kk) {
            const int slot = kk & 7;
            ulonglong2 h0 = p0[slot], h1 = p1[slot];
            p0[slot] = *(const ulonglong2*)(hq + (kbase + kk + 8) * 64);
            p1[slot] = *(const ulonglong2*)(hq + (kbase + kk + 8) * 64 + 4);
            ulonglong2 wv = *(const ulonglong2*)(wsm + (kbase + kk) * 8 + 2 * ng);
            fma2(acc[0][0], h0.x, wv.x);
            fma2(acc[0][1], h0.y, wv.x);
            fma2(acc[0][2], h1.x, wv.x);
            fma2(acc[0][3], h1.y, wv.x);
            fma2(acc[1][0], h0.x, wv.y);
            fma2(acc[1][1], h0.y, wv.y);
            fma2(acc[1][2], h1.x, wv.y);
            fma2(acc[1][3], h1.y, wv.y);
        }

        // Stash partials (lane-contiguous -> conflict-free STS.64).
#pragma unroll
        for (int j = 0; j < 2; j++)
#pragma unroll
            for (int i = 0; i < 4; i++)
                red[((warp * 8) + (j * 4 + i)) * 32 + lane] = acc[j][i];
        __syncthreads();

        if (tid < 256) {
            float sx = 0.f, sy = 0.f;
#pragma unroll
            for (int w2 = 0; w2 < 16; ++w2) {
                float2 v = unpack2(red[(w2 * 8 + rq) * 32 + rl]);
                sx += v.x; sy += v.y;
            }
            float r0 = tanhf(sx + pr0);
            float r1 = tanhf(sy + pr1);

            g_H[pb0 + (size_t)s * NF] = r0;
            g_H[pb1 + (size_t)s * NF] = r1;
            float* rc = g_ring + (s & 1) * (1032 * 64);
            *(float2*)(rc + rn * 64 + rb) = make_float2(r0, r1);
        }

        if (s != NS - 1) {
            __syncthreads();
            if (tid == 0) {
                __threadfence();
                atomicAdd(&g_ctr[s], 1u);
                unsigned v;
                do {
                    asm volatile("ld.acquire.gpu.global.u32 %0, [%1];"
                                 : "=r"(v) : "l"(&g_ctr[s]));
                } while (v < 128u);
            }
            __syncthreads();
        }
    }
}

extern "C" void kernel_launch(void* const* d_in, const int* in_sizes, int n_in,
                              void* d_out, int out_size)
{
    const float* x   = (const float*)d_in[0];
    const float* h0  = (const float*)d_in[1];
    const float* Wih = (const float*)d_in[2];
    const float* bih = (const float*)d_in[3];
    const float* Who = (const float*)d_in[4];
    const float* bho = (const float*)d_in[5];
    float* out = (float*)d_out;

    float *pP = nullptr, *pH = nullptr;
    cudaGetSymbolAddress((void**)&pP, g_P);
    cudaGetSymbolAddress((void**)&pH, g_H);

    static bool attr_done = false;
    if (!attr_done) {
        cudaFuncSetAttribute(rnn_scan, cudaFuncAttributeMaxDynamicSharedMemorySize, 98304);
        attr_done = true;
    }

    // 0) init ring slot 1 with transposed h0; zero barrier counters
    scan_init<<<256, 256>>>(h0);

    // 1) x_proj
    gemm_bias<<<dim3(8, 256), 256>>>(x, Wih, 2048, bih, pP);

    // 2) persistent recurrence scan
    rnn_scan<<<128, 512, 98304>>>(Wih);

    // 3) output projection
    gemm_bias<<<dim3(8, 256), 256>>>(pH, Who, 1024, bho, out);
}

// round 4
// speedup vs baseline: 2.8776x; 1.4855x over previous
#include <cuda_runtime.h>
#include <math.h>

#define NB 64
#define NS 512
#define NF 1024

static __device__ float g_P[NB * NS * NF];      // x_proj, [b][s][h]
static __device__ float g_H[NB * NS * NF];      // hidden states, [b][s][h]
static __device__ float g_ring[2 * 1032 * 64];  // transposed h ring: [slot][k][b]
static __device__ unsigned g_ctr[NS];           // per-step arrival counters

typedef unsigned long long ull;

__device__ __forceinline__ ull pack2(float x) {
    ull r;
    asm("mov.b64 %0, {%1, %1};" : "=l"(r) : "f"(x));
    return r;
}
__device__ __forceinline__ float2 unpack2(ull v) {
    float2 r;
    asm("mov.b64 {%0, %1}, %2;" : "=f"(r.x), "=f"(r.y) : "l"(v));
    return r;
}
__device__ __forceinline__ void fma2(ull& d, ull a, ull b) {
    asm("fma.rn.f32x2 %0, %1, %2, %0;" : "+l"(d) : "l"(a), "l"(b));
}

__global__ void knop() {}

// ---------------------------------------------------------------------------
// Big GEMM with bias (unchanged from round 3): 128x128 CTA tile, 8m x 8n.
// ---------------------------------------------------------------------------
__global__ void __launch_bounds__(256, 2) gemm_bias(
    const float* __restrict__ A, const float* __restrict__ W, int ldw,
    const float* __restrict__ bias, float* __restrict__ C)
{
    __shared__ __align__(16) float As[16][132];
    __shared__ __align__(16) float Bs[16][132];

    const int bm = blockIdx.y * 128;
    const int bn = blockIdx.x * 128;
    const int tid = threadIdx.x;

    const int lrow = tid >> 1, lkc = (tid & 1) << 3;
    const float* Ap = A + (size_t)(bm + lrow) * 1024 + lkc;
    const float* Wp = W + (size_t)(bn + lrow) * ldw + lkc;

    const int tx = tid & 15, ty = tid >> 4;
    const int m0 = ty * 8;
    const int nA = tx * 4;
    const int nBq = 64 + tx * 4;

    ull acc[8][4];
#pragma unroll
    for (int i = 0; i < 8; i++)
#pragma unroll
        for (int j = 0; j < 4; j++) acc[i][j] = 0ull;

    for (int k0 = 0; k0 < 1024; k0 += 16) {
        float4 av0 = *(const float4*)(Ap + k0);
        float4 av1 = *(const float4*)(Ap + k0 + 4);
        float4 bv0 = *(const float4*)(Wp + k0);
        float4 bv1 = *(const float4*)(Wp + k0 + 4);
        __syncthreads();
        As[lkc + 0][lrow] = av0.x; As[lkc + 1][lrow] = av0.y;
        As[lkc + 2][lrow] = av0.z; As[lkc + 3][lrow] = av0.w;
        As[lkc + 4][lrow] = av1.x; As[lkc + 5][lrow] = av1.y;
        As[lkc + 6][lrow] = av1.z; As[lkc + 7][lrow] = av1.w;
        Bs[lkc + 0][lrow] = bv0.x; Bs[lkc + 1][lrow] = bv0.y;
        Bs[lkc + 2][lrow] = bv0.z; Bs[lkc + 3][lrow] = bv0.w;
        Bs[lkc + 4][lrow] = bv1.x; Bs[lkc + 5][lrow] = bv1.y;
        Bs[lkc + 6][lrow] = bv1.z; Bs[lkc + 7][lrow] = bv1.w;
        __syncthreads();
#pragma unroll
        for (int k = 0; k < 16; k++) {
            float4 a0 = *(const float4*)&As[k][m0];
            float4 a1 = *(const float4*)&As[k][m0 + 4];
            ull ad[8];
            ad[0] = pack2(a0.x); ad[1] = pack2(a0.y);
            ad[2] = pack2(a0.z); ad[3] = pack2(a0.w);
            ad[4] = pack2(a1.x); ad[5] = pack2(a1.y);
            ad[6] = pack2(a1.z); ad[7] = pack2(a1.w);
            ulonglong2 bp0 = *(const ulonglong2*)&Bs[k][nA];
            ulonglong2 bp1 = *(const ulonglong2*)&Bs[k][nBq];
#pragma unroll
            for (int m = 0; m < 8; m++) {
                fma2(acc[m][0], ad[m], bp0.x);
                fma2(acc[m][1], ad[m], bp0.y);
                fma2(acc[m][2], ad[m], bp1.x);
                fma2(acc[m][3], ad[m], bp1.y);
            }
        }
    }

    float4 bbA = *(const float4*)(bias + bn + nA);
    float4 bbB = *(const float4*)(bias + bn + nBq);

#pragma unroll
    for (int m = 0; m < 8; m++) {
        float2 c0 = unpack2(acc[m][0]);
        float2 c1 = unpack2(acc[m][1]);
        float2 c2 = unpack2(acc[m][2]);
        float2 c3 = unpack2(acc[m][3]);
        float* cp = C + (size_t)(bm + m0 + m) * 1024 + bn;
        *(float4*)(cp + nA)  = make_float4(c0.x + bbA.x, c0.y + bbA.y,
                                           c1.x + bbA.z, c1.y + bbA.w);
        *(float4*)(cp + nBq) = make_float4(c2.x + bbB.x, c2.y + bbB.y,
                                           c3.x + bbB.z, c3.y + bbB.w);
    }
}

// ---------------------------------------------------------------------------
// Init: zero per-step counters; transpose h0 into ring slot 1.
// ---------------------------------------------------------------------------
__global__ void scan_init(const float* __restrict__ h0)
{
    int idx = blockIdx.x * 256 + threadIdx.x;   // 0 .. 65535
    int k = idx >> 6, b = idx & 63;
    g_ring[1032 * 64 + k * 64 + b] = h0[b * 1024 + k];
    if (idx < NS) g_ctr[idx] = 0u;
}

// ---------------------------------------------------------------------------
// Persistent recurrence scan: 128 CTAs x 512 threads (16 warps).
// CTA owns n-slice [c*8, c*8+8); W_h slice dup'd as (w,w) in SMEM (64 KB).
// Warp w reduces k in [w*64, w*64+64).
// Thread tile: 4 batches (ONE ulonglong2 = one LDG.128 per kk) x 4 n.
// Lane map: bpg = lane&15 (batches 4*bpg..+3), ng = lane>>4 (n offset 4*ng).
// Depth-8 pipeline = 32 prefetch regs (no spill). 8 FFMA(f32x2)/kk.
// Cross-warp reduce via 32 KB SMEM; g_H writes + g_P prefetch overlap the
// grid-barrier spin.
// ---------------------------------------------------------------------------
__global__ void __launch_bounds__(512, 1) rnn_scan(const float* __restrict__ Wih)
{
    extern __shared__ ull sm[];
    ull* wsm = sm;           // [1024 k][8 n] duplicated W_h slice (64 KB)
    ull* red = sm + 8192;    // [16 w][8 q][32 lane] partials (32 KB)

    const int tid  = threadIdx.x;
    const int warp = tid >> 5, lane = tid & 31;
    const int bpg = lane & 15;           // batches [4*bpg, 4*bpg+4)
    const int ng  = lane >> 4;           // n offset 4*ng within CTA slice
    const int kbase = warp * 64;
    const int NB0 = blockIdx.x * 8;

    // Load + duplicate this CTA's W_h slice (once per launch).
    for (int idx = tid; idx < 8192; idx += 512) {
        int k = idx >> 3, n = idx & 7;
        wsm[idx] = pack2(Wih[(size_t)(NB0 + n) * 2048 + 1024 + k]);
    }

    // Writer decode (threads 0..255 each own one f32x2 output pair).
    const int rq = tid >> 5, rl = tid & 31;          // valid when tid < 256
    const int rn = NB0 + 4 * (rl >> 4) + (rq >> 1);  // global n
    const int rb = 4 * (rl & 15) + 2 * (rq & 1);     // even batch
    const size_t pb0 = ((size_t)rb * NS) * NF + rn;
    const size_t pb1 = ((size_t)(rb + 1) * NS) * NF + rn;

    __syncthreads();

    float pr0 = 0.f, pr1 = 0.f;
    if (tid < 256) {
        pr0 = __ldg(&g_P[pb0]);
        pr1 = __ldg(&g_P[pb1]);
    }

    for (int s = 0; s < NS; ++s) {
        const float* __restrict__ hq =
            g_ring + ((s + 1) & 1) * (1032 * 64) + 4 * bpg;

        ull acc[4][2];
#pragma unroll
        for (int j = 0; j < 4; j++) { acc[j][0] = 0ull; acc[j][1] = 0ull; }

        // depth-8 pipelined k loop (ring rows padded: over-read harmless)
        ulonglong2 p[8];
#pragma unroll
        for (int j = 0; j < 8; ++j)
            p[j] = *(const ulonglong2*)(hq + (kbase + j) * 64);
#pragma unroll 8
        for (int kk = 0; kk < 64; ++kk) {
            const int slot = kk & 7;
            ulonglong2 h = p[slot];
            p[slot] = *(const ulonglong2*)(hq + (kbase + kk + 8) * 64);
            const ull* wr = wsm + (kbase + kk) * 8 + 4 * ng;
            ulonglong2 w0 = *(const ulonglong2*)wr;
            ulonglong2 w1 = *(const ulonglong2*)(wr + 2);
            fma2(acc[0][0], h.x, w0.x); fma2(acc[0][1], h.y, w0.x);
            fma2(acc[1][0], h.x, w0.y); fma2(acc[1][1], h.y, w0.y);
            fma2(acc[2][0], h.x, w1.x); fma2(acc[2][1], h.y, w1.x);
            fma2(acc[3][0], h.x, w1.y); fma2(acc[3][1], h.y, w1.y);
        }

        // Stash partials (lane-contiguous -> conflict-free STS.64).
#pragma unroll
        for (int j = 0; j < 4; j++)
#pragma unroll
            for (int bp = 0; bp < 2; bp++)
                red[((warp * 8) + (j * 2 + bp)) * 32 + lane] = acc[j][bp];
        __syncthreads();

        float r0 = 0.f, r1 = 0.f;
        if (tid < 256) {
            float sx = 0.f, sy = 0.f;
#pragma unroll
            for (int w2 = 0; w2 < 16; ++w2) {
                float2 v = unpack2(red[(w2 * 8 + rq) * 32 + rl]);
                sx += v.x; sy += v.y;
            }
            r0 = tanhf(sx + pr0);
            r1 = tanhf(sy + pr1);
            // Ring write first: it's what the next step needs.
            float* rc = g_ring + (s & 1) * (1032 * 64);
            *(float2*)(rc + rn * 64 + rb) = make_float2(r0, r1);
        }

        if (s != NS - 1) {
            __syncthreads();                 // all ring writes done CTA-wide
            if (tid == 0) {
                __threadfence();             // publish ring writes
                atomicAdd(&g_ctr[s], 1u);    // arrive
            }
            // Overlap with barrier wait: g_H write + next-step g_P prefetch.
            if (tid < 256) {
                g_H[pb0 + (size_t)s * NF] = r0;
                g_H[pb1 + (size_t)s * NF] = r1;
                pr0 = __ldg(&g_P[pb0 + (size_t)(s + 1) * NF]);
                pr1 = __ldg(&g_P[pb1 + (size_t)(s + 1) * NF]);
            }
            if (tid == 0) {
                unsigned v;
                do {
                    asm volatile("ld.acquire.gpu.global.u32 %0, [%1];"
                                 : "=r"(v) : "l"(&g_ctr[s]));
                } while (v < 128u);
            }
            __syncthreads();
        } else {
            if (tid < 256) {
                g_H[pb0 + (size_t)s * NF] = r0;
                g_H[pb1 + (size_t)s * NF] = r1;
            }
        }
    }
}

extern "C" void kernel_launch(void* const* d_in, const int* in_sizes, int n_in,
                              void* d_out, int out_size)
{
    const float* x   = (const float*)d_in[0];
    const float* h0  = (const float*)d_in[1];
    const float* Wih = (const float*)d_in[2];
    const float* bih = (const float*)d_in[3];
    const float* Who = (const float*)d_in[4];
    const float* bho = (const float*)d_in[5];
    float* out = (float*)d_out;

    float *pP = nullptr, *pH = nullptr;
    cudaGetSymbolAddress((void**)&pP, g_P);
    cudaGetSymbolAddress((void**)&pH, g_H);

    static bool attr_done = false;
    if (!attr_done) {
        cudaFuncSetAttribute(rnn_scan, cudaFuncAttributeMaxDynamicSharedMemorySize, 98304);
        attr_done = true;
    }

    // 0) init ring slot 1 with transposed h0; zero barrier counters
    scan_init<<<256, 256>>>(h0);

    // 1) x_proj
    gemm_bias<<<dim3(8, 256), 256>>>(x, Wih, 2048, bih, pP);

    // launch-index padding so ncu (-s 5 -c 1) captures rnn_scan (idx 5)
    knop<<<1, 32>>>();
    knop<<<1, 32>>>();
    knop<<<1, 32>>>();

    // 2) persistent recurrence scan
    rnn_scan<<<128, 512, 98304>>>(Wih);

    // 3) output projection
    gemm_bias<<<dim3(8, 256), 256>>>(pH, Who, 1024, bho, out);
}

// round 6
// speedup vs baseline: 3.7514x; 1.3036x over previous
#include <cuda_runtime.h>
#include <math.h>
#include <cstdint>

#define NB 64
#define NS 512
#define NF 1024
#define SST 36   // smem row stride in floats (36 mod 32 = 4 -> conflict-free frags)

static __device__ float g_P[NB * NS * NF];      // x_proj, [b][s][h]
static __device__ float g_H[NB * NS * NF];      // x_rounded, then hidden states (tf32-rounded)
static __device__ float g_Wx[NF * NF];          // tf32-rounded W_x
static __device__ float g_Who[NF * NF];         // tf32-rounded W_ho
static __device__ float g_ring[2 * 1032 * 64];  // transposed h ring
static __device__ unsigned g_ctr[NS];           // scan barrier counters

typedef unsigned long long ull;

__device__ __forceinline__ ull pack2(float x) {
    ull r; asm("mov.b64 %0, {%1, %1};" : "=l"(r) : "f"(x)); return r;
}
__device__ __forceinline__ float2 unpack2(ull v) {
    float2 r; asm("mov.b64 {%0, %1}, %2;" : "=f"(r.x), "=f"(r.y) : "l"(v)); return r;
}
__device__ __forceinline__ void fma2(ull& d, ull a, ull b) {
    asm("fma.rn.f32x2 %0, %1, %2, %0;" : "+l"(d) : "l"(a), "l"(b));
}
__device__ __forceinline__ float tf32r(float x) {
    float r; asm("cvt.rna.tf32.f32 %0, %1;" : "=f"(r) : "f"(x)); return r;
}
__device__ __forceinline__ uint32_t smem_u32(const void* p) {
    uint32_t a;
    asm("{ .reg .u64 t; cvta.to.shared.u64 t, %1; cvt.u32.u64 %0, t; }" : "=r"(a) : "l"(p));
    return a;
}
__device__ __forceinline__ void cp_async16(uint32_t dst, const void* src) {
    asm volatile("cp.async.cg.shared.global [%0], [%1], 16;" :: "r"(dst), "l"(src) : "memory");
}
__device__ __forceinline__ void mma_m16n8k8(float* c, const uint32_t* a,
                                            uint32_t b0, uint32_t b1) {
    asm volatile(
        "mma.sync.aligned.m16n8k8.row.col.f32.tf32.tf32.f32 "
        "{%0,%1,%2,%3}, {%4,%5,%6,%7}, {%8,%9}, {%0,%1,%2,%3};"
        : "+f"(c[0]), "+f"(c[1]), "+f"(c[2]), "+f"(c[3])
        : "r"(a[0]), "r"(a[1]), "r"(a[2]), "r"(a[3]), "r"(b0), "r"(b1));
}

__global__ void knop() {}

// ---------------------------------------------------------------------------
// tf32 mma.sync GEMM: C[M x 1024] = A[M x 1024] @ B[1024 x 1024]^T + bias
// A, B row-major, pre-rounded to tf32 (RN). CTA tile 128x128, BK=32,
// 256 threads (8 warps, warp tile 32m x 64n), cp.async 2-stage pipeline.
// SMEM layout per buffer: A[128][SST], B[128][SST] (row-major, k minor).
// ---------------------------------------------------------------------------
__global__ void __launch_bounds__(256, 2) gemm_mma(
    const float* __restrict__ A, const float* __restrict__ B,
    const float* __restrict__ bias, float* __restrict__ C)
{
    extern __shared__ float sm[];
    const int tid = threadIdx.x;
    const int wid = tid >> 5, lane = tid & 31;
    const int g = lane >> 2, tig = lane & 3;
    const int bm = blockIdx.y * 128, bn = blockIdx.x * 128;
    const int mbase = (wid >> 1) * 32, nbase = (wid & 1) * 64;

    // buffers: [st][A: 128*SST][B: 128*SST] floats
    const int BUF = 128 * SST;
    const uint32_t sbase = smem_u32(sm);

    // loader mapping: row = tid>>1 (0..127), k offset (tid&1)*16, 4x float4
    const int lrow = tid >> 1, lk = (tid & 1) * 16;
    const float* Ag = A + (size_t)(bm + lrow) * 1024 + lk;
    const float* Bg = B + (size_t)(bn + lrow) * 1024 + lk;
    const uint32_t dstA = sbase + (uint32_t)(lrow * SST + lk) * 4;
    const uint32_t dstB = dstA + (uint32_t)BUF * 4;

    float acc[2][8][4];
#pragma unroll
    for (int mt = 0; mt < 2; mt++)
#pragma unroll
        for (int nt = 0; nt < 8; nt++)
#pragma unroll
            for (int q = 0; q < 4; q++) acc[mt][nt][q] = 0.f;

    // issue stage 0
    {
        const float* ag = Ag; const float* bg = Bg;
#pragma unroll
        for (int j = 0; j < 4; j++) {
            cp_async16(dstA + j * 16, ag + 4 * j);
            cp_async16(dstB + j * 16, bg + 4 * j);
        }
        asm volatile("cp.async.commit_group;" ::: "memory");
    }

    for (int c = 0; c < 32; ++c) {
        if (c + 1 < 32) {
            const int st = (c + 1) & 1;
            const float* ag = Ag + (c + 1) * 32;
            const float* bg = Bg + (c + 1) * 32;
            const uint32_t off = (uint32_t)(st * 2 * BUF) * 4;
#pragma unroll
            for (int j = 0; j < 4; j++) {
                cp_async16(dstA + off + j * 16, ag + 4 * j);
                cp_async16(dstB + off + j * 16, bg + 4 * j);
            }
            asm volatile("cp.async.commit_group;" ::: "memory");
            asm volatile("cp.async.wait_group 1;" ::: "memory");
        } else {
            asm volatile("cp.async.wait_group 0;" ::: "memory");
        }
        __syncthreads();

        const float* As_ = sm + (c & 1) * 2 * BUF;
        const float* Bs_ = As_ + BUF;
#pragma unroll
        for (int ks = 0; ks < 4; ks++) {
            const int k = ks * 8;
            uint32_t a[2][4];
#pragma unroll
            for (int mt = 0; mt < 2; mt++) {
                const float* ap = As_ + (mbase + mt * 16 + g) * SST + k + tig;
                a[mt][0] = __float_as_uint(ap[0]);
                a[mt][1] = __float_as_uint(ap[8 * SST]);
                a[mt][2] = __float_as_uint(ap[4]);
                a[mt][3] = __float_as_uint(ap[8 * SST + 4]);
            }
#pragma unroll
            for (int nt = 0; nt < 8; nt++) {
                const float* bp = Bs_ + (nbase + nt * 8 + g) * SST + k + tig;
                uint32_t b0 = __float_as_uint(bp[0]);
                uint32_t b1 = __float_as_uint(bp[4]);
                mma_m16n8k8(acc[0][nt], a[0], b0, b1);
                mma_m16n8k8(acc[1][nt], a[1], b0, b1);
            }
        }
        __syncthreads();
    }

    // epilogue
#pragma unroll
    for (int mt = 0; mt < 2; mt++) {
        const size_t r0 = (size_t)(bm + mbase + mt * 16 + g) * 1024;
#pragma unroll
        for (int nt = 0; nt < 8; nt++) {
            const int col = bn + nbase + nt * 8 + 2 * tig;
            float2 bb = *(const float2*)&bias[col];
            float2 v0 = make_float2(acc[mt][nt][0] + bb.x, acc[mt][nt][1] + bb.y);
            float2 v1 = make_float2(acc[mt][nt][2] + bb.x, acc[mt][nt][3] + bb.y);
            *(float2*)&C[r0 + col] = v0;
            *(float2*)&C[r0 + 8 * 1024 + col] = v1;
        }
    }
}

// ---------------------------------------------------------------------------
// Conversions: RN-round weights and x to tf32.
// ---------------------------------------------------------------------------
__global__ void cvt_w(const float* __restrict__ Wih, const float* __restrict__ Who)
{
    int i = blockIdx.x * 256 + threadIdx.x;   // 0 .. 1M-1
    int n = i >> 10, k = i & 1023;
    g_Wx[i]  = tf32r(Wih[(size_t)n * 2048 + k]);
    g_Who[i] = tf32r(Who[i]);
}
__global__ void cvt_x(const float* __restrict__ x)
{
    int i = blockIdx.x * 256 + threadIdx.x;   // float4 idx
    float4 v = ((const float4*)x)[i];
    v.x = tf32r(v.x); v.y = tf32r(v.y); v.z = tf32r(v.z); v.w = tf32r(v.w);
    ((float4*)g_H)[i] = v;
}

// ---------------------------------------------------------------------------
// Init: zero per-step counters; transpose h0 into ring slot 1.
// ---------------------------------------------------------------------------
__global__ void scan_init(const float* __restrict__ h0)
{
    int idx = blockIdx.x * 256 + threadIdx.x;   // 0 .. 65535
    int k = idx >> 6, b = idx & 63;
    g_ring[1032 * 64 + k * 64 + b] = h0[b * 1024 + k];
    if (idx < NS) g_ctr[idx] = 0u;
}

// ---------------------------------------------------------------------------
// Persistent recurrence scan (round-4 version; g_H gets tf32-rounded h).
// ---------------------------------------------------------------------------
__global__ void __launch_bounds__(512, 1) rnn_scan(const float* __restrict__ Wih)
{
    extern __shared__ ull smu[];
    ull* wsm = smu;          // [1024 k][8 n] duplicated W_h slice (64 KB)
    ull* red = smu + 8192;   // [16 w][8 q][32 lane] partials (32 KB)

    const int tid  = threadIdx.x;
    const int warp = tid >> 5, lane = tid & 31;
    const int bpg = lane & 15;
    const int ng  = lane >> 4;
    const int kbase = warp * 64;
    const int NB0 = blockIdx.x * 8;

    for (int idx = tid; idx < 8192; idx += 512) {
        int k = idx >> 3, n = idx & 7;
        wsm[idx] = pack2(Wih[(size_t)(NB0 + n) * 2048 + 1024 + k]);
    }

    const int rq = tid >> 5, rl = tid & 31;
    const int rn = NB0 + 4 * (rl >> 4) + (rq >> 1);
    const int rb = 4 * (rl & 15) + 2 * (rq & 1);
    const size_t pb0 = ((size_t)rb * NS) * NF + rn;
    const size_t pb1 = ((size_t)(rb + 1) * NS) * NF + rn;

    __syncthreads();

    float pr0 = 0.f, pr1 = 0.f;
    if (tid < 256) {
        pr0 = __ldg(&g_P[pb0]);
        pr1 = __ldg(&g_P[pb1]);
    }

    for (int s = 0; s < NS; ++s) {
        const float* __restrict__ hq =
            g_ring + ((s + 1) & 1) * (1032 * 64) + 4 * bpg;

        ull acc[4][2];
#pragma unroll
        for (int j = 0; j < 4; j++) { acc[j][0] = 0ull; acc[j][1] = 0ull; }

        ulonglong2 p[8];
#pragma unroll
        for (int j = 0; j < 8; ++j)
            p[j] = *(const ulonglong2*)(hq + (kbase + j) * 64);
#pragma unroll 8
        for (int kk = 0; kk < 64; ++kk) {
            const int slot = kk & 7;
            ulonglong2 h = p[slot];
            p[slot] = *(const ulonglong2*)(hq + (kbase + kk + 8) * 64);
            const ull* wr = wsm + (kbase + kk) * 8 + 4 * ng;
            ulonglong2 w0 = *(const ulonglong2*)wr;
            ulonglong2 w1 = *(const ulonglong2*)(wr + 2);
            fma2(acc[0][0], h.x, w0.x); fma2(acc[0][1], h.y, w0.x);
            fma2(acc[1][0], h.x, w0.y); fma2(acc[1][1], h.y, w0.y);
            fma2(acc[2][0], h.x, w1.x); fma2(acc[2][1], h.y, w1.x);
            fma2(acc[3][0], h.x, w1.y); fma2(acc[3][1], h.y, w1.y);
        }

#pragma unroll
        for (int j = 0; j < 4; j++)
#pragma unroll
            for (int bp = 0; bp < 2; bp++)
                red[((warp * 8) + (j * 2 + bp)) * 32 + lane] = acc[j][bp];
        __syncthreads();

        float r0 = 0.f, r1 = 0.f;
        if (tid < 256) {
            float sx = 0.f, sy = 0.f;
#pragma unroll
            for (int w2 = 0; w2 < 16; ++w2) {
                float2 v = unpack2(red[(w2 * 8 + rq) * 32 + rl]);
                sx += v.x; sy += v.y;
            }
            r0 = tanhf(sx + pr0);
            r1 = tanhf(sy + pr1);
            float* rc = g_ring + (s & 1) * (1032 * 64);
            *(float2*)(rc + rn * 64 + rb) = make_float2(r0, r1);
        }

        if (s != NS - 1) {
            __syncthreads();
            if (tid == 0) {
                __threadfence();
                atomicAdd(&g_ctr[s], 1u);
            }
            if (tid < 256) {
                g_H[pb0 + (size_t)s * NF] = tf32r(r0);
                g_H[pb1 + (size_t)s * NF] = tf32r(r1);
                pr0 = __ldg(&g_P[pb0 + (size_t)(s + 1) * NF]);
                pr1 = __ldg(&g_P[pb1 + (size_t)(s + 1) * NF]);
            }
            if (tid == 0) {
                unsigned v;
                do {
                    asm volatile("ld.acquire.gpu.global.u32 %0, [%1];"
                                 : "=r"(v) : "l"(&g_ctr[s]));
                } while (v < 128u);
            }
            __syncthreads();
        } else {
            if (tid < 256) {
                g_H[pb0 + (size_t)s * NF] = tf32r(r0);
                g_H[pb1 + (size_t)s * NF] = tf32r(r1);
            }
        }
    }
}

extern "C" void kernel_launch(void* const* d_in, const int* in_sizes, int n_in,
                              void* d_out, int out_size)
{
    const float* x   = (const float*)d_in[0];
    const float* h0  = (const float*)d_in[1];
    const float* Wih = (const float*)d_in[2];
    const float* bih = (const float*)d_in[3];
    const float* Who = (const float*)d_in[4];
    const float* bho = (const float*)d_in[5];
    float* out = (float*)d_out;

    float *pP = nullptr, *pH = nullptr, *pWx = nullptr, *pWo = nullptr;
    cudaGetSymbolAddress((void**)&pP, g_P);
    cudaGetSymbolAddress((void**)&pH, g_H);
    cudaGetSymbolAddress((void**)&pWx, g_Wx);
    cudaGetSymbolAddress((void**)&pWo, g_Who);

    const int GEMM_SMEM = 4 * 128 * SST * 4;   // 73728 B

    static bool attr_done = false;
    if (!attr_done) {
        cudaFuncSetAttribute(rnn_scan, cudaFuncAttributeMaxDynamicSharedMemorySize, 98304);
        cudaFuncSetAttribute(gemm_mma, cudaFuncAttributeMaxDynamicSharedMemorySize, GEMM_SMEM);
        attr_done = true;
    }

    // idx 0: init ring slot 1 + barrier counters
    scan_init<<<256, 256>>>(h0);
    // idx 1: round weights to tf32
    cvt_w<<<4096, 256>>>(Wih, Who);
    // idx 2: round x to tf32 into g_H
    cvt_x<<<32768, 256>>>(x);
    // idx 3: x_proj = x_r @ W_x^T + b_ih  -> g_P
    gemm_mma<<<dim3(8, 256), 256, GEMM_SMEM>>>(pH, pWx, bih, pP);
    // idx 4: padding so ncu -s 5 captures the scan
    knop<<<1, 32>>>();
    // idx 5: persistent recurrence scan
    rnn_scan<<<128, 512, 98304>>>(Wih);
    // idx 6: out = h_r @ W_ho^T + b_ho
    gemm_mma<<<dim3(8, 256), 256, GEMM_SMEM>>>(pH, pWo, bho, out);
}

// round 7
// speedup vs baseline: 4.2513x; 1.1333x over previous
#include <cuda_runtime.h>
#include <math.h>
#include <cstdint>

#define NB 64
#define NS 512
#define NF 1024
#define SST 36   // gemm smem row stride in floats

static __device__ float g_P[NB * NS * NF];      // x_proj, [b][s][h]
static __device__ float g_H[NB * NS * NF];      // x_rounded, then hidden states (tf32-rounded)
static __device__ float g_Wx[NF * NF];          // tf32-rounded W_x
static __device__ float g_Who[NF * NF];         // tf32-rounded W_ho
static __device__ float g_ring[2 * 1032 * 64];  // transposed h ring [slot][k][b]
static __device__ unsigned g_ctr[2 * NS];       // per-(step,group) arrival counters

typedef unsigned long long ull;

__device__ __forceinline__ ull pack2(float x) {
    ull r; asm("mov.b64 %0, {%1, %1};" : "=l"(r) : "f"(x)); return r;
}
__device__ __forceinline__ float2 unpack2(ull v) {
    float2 r; asm("mov.b64 {%0, %1}, %2;" : "=f"(r.x), "=f"(r.y) : "l"(v)); return r;
}
__device__ __forceinline__ void fma2(ull& d, ull a, ull b) {
    asm("fma.rn.f32x2 %0, %1, %2, %0;" : "+l"(d) : "l"(a), "l"(b));
}
__device__ __forceinline__ float tf32r(float x) {
    float r; asm("cvt.rna.tf32.f32 %0, %1;" : "=f"(r) : "f"(x)); return r;
}
__device__ __forceinline__ uint32_t smem_u32(const void* p) {
    uint32_t a;
    asm("{ .reg .u64 t; cvta.to.shared.u64 t, %1; cvt.u32.u64 %0, t; }" : "=r"(a) : "l"(p));
    return a;
}
__device__ __forceinline__ void cp_async16(uint32_t dst, const void* src) {
    asm volatile("cp.async.cg.shared.global [%0], [%1], 16;" :: "r"(dst), "l"(src) : "memory");
}
__device__ __forceinline__ void mma_m16n8k8(float* c, const uint32_t* a,
                                            uint32_t b0, uint32_t b1) {
    asm volatile(
        "mma.sync.aligned.m16n8k8.row.col.f32.tf32.tf32.f32 "
        "{%0,%1,%2,%3}, {%4,%5,%6,%7}, {%8,%9}, {%0,%1,%2,%3};"
        : "+f"(c[0]), "+f"(c[1]), "+f"(c[2]), "+f"(c[3])
        : "r"(a[0]), "r"(a[1]), "r"(a[2]), "r"(a[3]), "r"(b0), "r"(b1));
}

__global__ void knop() {}

// ---------------------------------------------------------------------------
// Fused init (user launch 0): tf32-round x -> g_H, round weights, init ring
// slot 1 with transposed h0, zero barrier counters.
// ---------------------------------------------------------------------------
__global__ void fused_init(const float* __restrict__ x,
                           const float* __restrict__ Wih,
                           const float* __restrict__ Who,
                           const float* __restrict__ h0)
{
    int i = blockIdx.x * 256 + threadIdx.x;   // 0 .. 8388607 (float4 idx)
    float4 v = ((const float4*)x)[i];
    v.x = tf32r(v.x); v.y = tf32r(v.y); v.z = tf32r(v.z); v.w = tf32r(v.w);
    ((float4*)g_H)[i] = v;

    if (i < NF * NF) {
        int n = i >> 10, k = i & 1023;
        g_Wx[i]  = tf32r(Wih[(size_t)n * 2048 + k]);
        g_Who[i] = tf32r(Who[i]);
    }
    if (i < 65536) {
        int k = i >> 6, b = i & 63;
        g_ring[1032 * 64 + k * 64 + b] = h0[b * 1024 + k];
    }
    if (i < 2 * NS) g_ctr[i] = 0u;
}

// ---------------------------------------------------------------------------
// tf32 mma.sync GEMM (unchanged from round 6).
// ---------------------------------------------------------------------------
__global__ void __launch_bounds__(256, 2) gemm_mma(
    const float* __restrict__ A, const float* __restrict__ B,
    const float* __restrict__ bias, float* __restrict__ C)
{
    extern __shared__ float sm[];
    const int tid = threadIdx.x;
    const int wid = tid >> 5, lane = tid & 31;
    const int g = lane >> 2, tig = lane & 3;
    const int bm = blockIdx.y * 128, bn = blockIdx.x * 128;
    const int mbase = (wid >> 1) * 32, nbase = (wid & 1) * 64;

    const int BUF = 128 * SST;
    const uint32_t sbase = smem_u32(sm);

    const int lrow = tid >> 1, lk = (tid & 1) * 16;
    const float* Ag = A + (size_t)(bm + lrow) * 1024 + lk;
    const float* Bg = B + (size_t)(bn + lrow) * 1024 + lk;
    const uint32_t dstA = sbase + (uint32_t)(lrow * SST + lk) * 4;
    const uint32_t dstB = dstA + (uint32_t)BUF * 4;

    float acc[2][8][4];
#pragma unroll
    for (int mt = 0; mt < 2; mt++)
#pragma unroll
        for (int nt = 0; nt < 8; nt++)
#pragma unroll
            for (int q = 0; q < 4; q++) acc[mt][nt][q] = 0.f;

    {
#pragma unroll
        for (int j = 0; j < 4; j++) {
            cp_async16(dstA + j * 16, Ag + 4 * j);
            cp_async16(dstB + j * 16, Bg + 4 * j);
        }
        asm volatile("cp.async.commit_group;" ::: "memory");
    }

    for (int c = 0; c < 32; ++c) {
        if (c + 1 < 32) {
            const int st = (c + 1) & 1;
            const float* ag = Ag + (c + 1) * 32;
            const float* bg = Bg + (c + 1) * 32;
            const uint32_t off = (uint32_t)(st * 2 * BUF) * 4;
#pragma unroll
            for (int j = 0; j < 4; j++) {
                cp_async16(dstA + off + j * 16, ag + 4 * j);
                cp_async16(dstB + off + j * 16, bg + 4 * j);
            }
            asm volatile("cp.async.commit_group;" ::: "memory");
            asm volatile("cp.async.wait_group 1;" ::: "memory");
        } else {
            asm volatile("cp.async.wait_group 0;" ::: "memory");
        }
        __syncthreads();

        const float* As_ = sm + (c & 1) * 2 * BUF;
        const float* Bs_ = As_ + BUF;
#pragma unroll
        for (int ks = 0; ks < 4; ks++) {
            const int k = ks * 8;
            uint32_t a[2][4];
#pragma unroll
            for (int mt = 0; mt < 2; mt++) {
                const float* ap = As_ + (mbase + mt * 16 + g) * SST + k + tig;
                a[mt][0] = __float_as_uint(ap[0]);
                a[mt][1] = __float_as_uint(ap[8 * SST]);
                a[mt][2] = __float_as_uint(ap[4]);
                a[mt][3] = __float_as_uint(ap[8 * SST + 4]);
            }
#pragma unroll
            for (int nt = 0; nt < 8; nt++) {
                const float* bp = Bs_ + (nbase + nt * 8 + g) * SST + k + tig;
                uint32_t b0 = __float_as_uint(bp[0]);
                uint32_t b1 = __float_as_uint(bp[4]);
                mma_m16n8k8(acc[0][nt], a[0], b0, b1);
                mma_m16n8k8(acc[1][nt], a[1], b0, b1);
            }
        }
        __syncthreads();
    }

#pragma unroll
    for (int mt = 0; mt < 2; mt++) {
        const size_t r0 = (size_t)(bm + mbase + mt * 16 + g) * 1024;
#pragma unroll
        for (int nt = 0; nt < 8; nt++) {
            const int col = bn + nbase + nt * 8 + 2 * tig;
            float2 bb = *(const float2*)&bias[col];
            float2 v0 = make_float2(acc[mt][nt][0] + bb.x, acc[mt][nt][1] + bb.y);
            float2 v1 = make_float2(acc[mt][nt][2] + bb.x, acc[mt][nt][3] + bb.y);
            *(float2*)&C[r0 + col] = v0;
            *(float2*)&C[r0 + 8 * 1024 + col] = v1;
        }
    }
}

// ---------------------------------------------------------------------------
// Persistent recurrence scan, batch-split: 128 CTAs x 512 threads, 2 groups
// of 64 CTAs. Group g owns batches [32g, 32g+32); CTA owns 16 n. W_h slice
// stored n-major UNduplicated in SMEM (64 KB). Warp w reduces k in
// [64w, 64w+64). Thread tile: 4 batches (one LDG.128 from ring) x 4 n
// (one LDS.128, two n-pair f32x2 accs per batch). h dup'd in regs (4 movs/kk).
// Halves per-step L2 h-traffic (16 MB) and barrier scope (64 arrivals).
// ---------------------------------------------------------------------------
__global__ void __launch_bounds__(512, 1) rnn_scan(const float* __restrict__ Wih)
{
    extern __shared__ float smf[];
    float* wsm = smf;                    // [1024 k][16 n] n-major (64 KB)
    ull* red = (ull*)(smf + 16384);      // [16 w][8 q][32 lane] (32 KB)

    const int tid  = threadIdx.x;
    const int warp = tid >> 5, lane = tid & 31;
    const int bq = lane & 7;             // 4-batch group within 32
    const int nq = lane >> 3;            // 4-n group within 16
    const int kbase = warp * 64;
    const int grp = blockIdx.x & 1;      // batch group
    const int NB0 = (blockIdx.x >> 1) * 16;
    const int B0  = grp * 32;

    // Load W_h slice transposed to [k][16n] (coalesced LDG; one-time STS).
    for (int idx = tid; idx < 16384; idx += 512) {
        int n = idx >> 10, k = idx & 1023;
        wsm[k * 16 + n] = Wih[(size_t)(NB0 + n) * 2048 + 1024 + k];
    }

    // Writer decode (threads 0..255 own one n-pair for one batch).
    const int rq = tid >> 5, rl = tid & 31;          // valid for tid < 256
    const int rb = B0 + 4 * (rl & 7) + (rq >> 1);    // batch
    const int rn = NB0 + 4 * (rl >> 3) + 2 * (rq & 1); // even n
    const size_t pb = ((size_t)rb * NS) * NF + rn;

    __syncthreads();

    float2 pr = make_float2(0.f, 0.f);
    if (tid < 256) pr = *(const float2*)&g_P[pb];

    for (int s = 0; s < NS; ++s) {
        const float* __restrict__ hq =
            g_ring + ((s + 1) & 1) * (1032 * 64) + B0 + 4 * bq;

        ull acc[4][2];
#pragma unroll
        for (int i = 0; i < 4; i++) { acc[i][0] = 0ull; acc[i][1] = 0ull; }

        float4 pf[8];
#pragma unroll
        for (int j = 0; j < 8; ++j)
            pf[j] = *(const float4*)(hq + (kbase + j) * 64);
#pragma unroll 8
        for (int kk = 0; kk < 64; ++kk) {
            const int slot = kk & 7;
            float4 h = pf[slot];
            pf[slot] = *(const float4*)(hq + (kbase + kk + 8) * 64);
            ulonglong2 w = *(const ulonglong2*)(wsm + (kbase + kk) * 16 + 4 * nq);
            ull h0d = pack2(h.x), h1d = pack2(h.y);
            ull h2d = pack2(h.z), h3d = pack2(h.w);
            fma2(acc[0][0], h0d, w.x); fma2(acc[0][1], h0d, w.y);
            fma2(acc[1][0], h1d, w.x); fma2(acc[1][1], h1d, w.y);
            fma2(acc[2][0], h2d, w.x); fma2(acc[2][1], h2d, w.y);
            fma2(acc[3][0], h3d, w.x); fma2(acc[3][1], h3d, w.y);
        }

        // Stash partials (lane-contiguous, conflict-free).
#pragma unroll
        for (int i = 0; i < 4; i++)
#pragma unroll
            for (int p = 0; p < 2; p++)
                red[((warp * 8) + (i * 2 + p)) * 32 + lane] = acc[i][p];
        __syncthreads();

        float r0 = 0.f, r1 = 0.f;
        if (tid < 256) {
            float sx = 0.f, sy = 0.f;
#pragma unroll
            for (int w2 = 0; w2 < 16; ++w2) {
                float2 v = unpack2(red[(w2 * 8 + rq) * 32 + rl]);
                sx += v.x; sy += v.y;
            }
            r0 = tanhf(sx + pr.x);
            r1 = tanhf(sy + pr.y);
            // Ring write first: next step depends on it. (n-pair -> 2 rows)
            float* rc = g_ring + (s & 1) * (1032 * 64);
            rc[rn * 64 + rb] = r0;
            rc[(rn + 1) * 64 + rb] = r1;
        }

        if (s != NS - 1) {
            __syncthreads();                    // group-owned ring rows done
            if (tid == 0) {
                asm volatile("red.release.gpu.global.add.u32 [%0], %1;"
                             :: "l"(&g_ctr[s * 2 + grp]), "r"(1u) : "memory");
            }
            // Overlapped with the barrier: g_H write + next g_P prefetch.
            if (tid < 256) {
                *(float2*)&g_H[pb + (size_t)s * NF] =
                    make_float2(tf32r(r0), tf32r(r1));
                pr = *(const float2*)&g_P[pb + (size_t)(s + 1) * NF];
            }
            if (tid == 0) {
                unsigned v;
                do {
                    asm volatile("ld.acquire.gpu.global.u32 %0, [%1];"
                                 : "=r"(v) : "l"(&g_ctr[s * 2 + grp]));
                } while (v < 64u);
            }
            __syncthreads();
        } else {
            if (tid < 256) {
                *(float2*)&g_H[pb + (size_t)s * NF] =
                    make_float2(tf32r(r0), tf32r(r1));
            }
        }
    }
}

extern "C" void kernel_launch(void* const* d_in, const int* in_sizes, int n_in,
                              void* d_out, int out_size)
{
    const float* x   = (const float*)d_in[0];
    const float* h0  = (const float*)d_in[1];
    const float* Wih = (const float*)d_in[2];
    const float* bih = (const float*)d_in[3];
    const float* Who = (const float*)d_in[4];
    const float* bho = (const float*)d_in[5];
    float* out = (float*)d_out;

    float *pP = nullptr, *pH = nullptr, *pWx = nullptr, *pWo = nullptr;
    cudaGetSymbolAddress((void**)&pP, g_P);
    cudaGetSymbolAddress((void**)&pH, g_H);
    cudaGetSymbolAddress((void**)&pWx, g_Wx);
    cudaGetSymbolAddress((void**)&pWo, g_Who);

    const int GEMM_SMEM = 4 * 128 * SST * 4;   // 73728 B

    static bool attr_done = false;
    if (!attr_done) {
        cudaFuncSetAttribute(rnn_scan, cudaFuncAttributeMaxDynamicSharedMemorySize, 98304);
        cudaFuncSetAttribute(gemm_mma, cudaFuncAttributeMaxDynamicSharedMemorySize, GEMM_SMEM);
        attr_done = true;
    }

    // user idx 0: fused init (cvt x + weights, ring slot 1, counters)
    fused_init<<<32768, 256>>>(x, Wih, Who, h0);
    // user idx 1: x_proj = x_r @ W_x^T + b_ih -> g_P
    gemm_mma<<<dim3(8, 256), 256, GEMM_SMEM>>>(pH, pWx, bih, pP);
    // user idx 2: pad so the profiler (captures user idx 3) hits the scan
    knop<<<1, 32>>>();
    // user idx 3: persistent recurrence scan  <-- ncu capture lands here
    rnn_scan<<<128, 512, 98304>>>(Wih);
    // user idx 4: out = h_r @ W_ho^T + b_ho
    gemm_mma<<<dim3(8, 256), 256, GEMM_SMEM>>>(pH, pWo, bho, out);
}